// round 9
// baseline (speedup 1.0000x reference)
#include <cuda_runtime.h>
#include <math.h>

#define HD     128
#define HEADS  4
#define CDIM   32
#define NLAYER 4
#define NEG    100
#define HS     128

#define N_MAX  2048
#define E_MAX  4096
#define B_MAX  32
#define BE_MAX (B_MAX * NEG)

#define GRID   296
#define TPB    256

// ---------------- scratch (device globals; no allocation allowed) ----------
__device__ float g_h   [N_MAX * HD];
__device__ float g_e   [E_MAX * HD];
__device__ float g_xl  [N_MAX * HD];
__device__ float g_ssrc[N_MAX * HEADS];
__device__ float g_sdst[N_MAX * HEADS];
__device__ float g_ae  [E_MAX * HEADS];
__device__ float g_aesum[HEADS];
__device__ float g_den  [N_MAX * HEADS];
__device__ float g_agg  [N_MAX * HD];
__device__ float g_onsite[N_MAX];
__device__ float g_coup  [E_MAX];
__device__ int   g_dna  [N_MAX];
__device__ int   g_loc  [N_MAX];
// NEGF scratch
__device__ float g_hbd[B_MAX * HS];
__device__ float g_hb1[B_MAX * HS];
__device__ float g_hb2[B_MAX * HS];
__device__ float g_dvb[B_MAX * HS];
__device__ float2 g_lu[BE_MAX * 5 * HS];
__device__ float g_Tacc[BE_MAX];
__device__ float g_Dacc[BE_MAX];
__device__ int   g_cnt [BE_MAX];
// grid barrier state
__device__ unsigned g_arrive;
__device__ volatile unsigned g_gen;

// complex mul / fms helpers
#define CMUL(o, a, b) do { \
    (o).x = (a).x * (b).x - (a).y * (b).y; \
    (o).y = (a).x * (b).y + (a).y * (b).x; \
} while (0)
#define CFMS(m, c, r) do { \
    (m).x = fmaf(-(c).x, (r).x, fmaf((c).y, (r).y, (m).x)); \
    (m).y = fmaf(-(c).x, (r).y, fmaf(-(c).y, (r).x, (m).y)); \
} while (0)

// software grid barrier; generation tracked in smem (s_gen), re-read per launch
__device__ __forceinline__ void gridbar(unsigned* s_gen) {
    __threadfence();
    __syncthreads();
    if (threadIdx.x == 0) {
        unsigned gen = *s_gen;
        unsigned old = atomicAdd(&g_arrive, 1u);
        if (old == GRID - 1u) {
            g_arrive = 0u;
            __threadfence();
            g_gen = gen + 1u;
        } else {
            while (g_gen == gen) __nanosleep(64);
        }
        *s_gen = gen + 1u;
    }
    __syncthreads();
}

// ---------------- persistent kernel: full GNN + assembly + banded LU -------
__global__ void __launch_bounds__(TPB, 2) k_pers(
    const float* __restrict__ x, const int* __restrict__ src,
    const int* __restrict__ dst, const float* __restrict__ ea,
    const int* __restrict__ batch,
    const float* __restrict__ GL, const float* __restrict__ GR,
    const float* __restrict__ node_w, const float* __restrict__ node_b,
    const float* __restrict__ edgep_w, const float* __restrict__ edgep_b,
    const float* __restrict__ gat_lin, const float* __restrict__ att_src,
    const float* __restrict__ att_dst, const float* __restrict__ gat_le,
    const float* __restrict__ att_ed, const float* __restrict__ gat_b,
    const float* __restrict__ ln_s, const float* __restrict__ ln_b,
    const float* __restrict__ on_w1, const float* __restrict__ on_b1,
    const float* __restrict__ on_w2, const float* __restrict__ on_b2,
    const float* __restrict__ cp_w1, const float* __restrict__ cp_b1,
    const float* __restrict__ cp_w2, const float* __restrict__ cp_b2,
    int N, int E, int B)
{
    __shared__ float rows[2][4][HD];
    __shared__ float outs[2][4][HD];
    __shared__ float redh[2][4], redv[2][4];
    __shared__ float rowbuf[8][HD];
    __shared__ int smi[N_MAX], sbt[N_MAX], slo[N_MAX];
    __shared__ unsigned s_gen;

    int tid = threadIdx.x, bid = blockIdx.x;
    int half = tid >> 7, t2 = tid & 127;
    int w2 = t2 >> 5, lane = t2 & 31;
    int gtid = bid * TPB + tid;
    int F = N + E;
    int BE = B * NEG;

    if (tid == 0) s_gen = g_gen;

    // ---- phase init: h, e projections; zero accumulators + bands ----------
    if (gtid < HEADS) g_aesum[gtid] = 0.f;
    for (int i = gtid; i < B * HS; i += GRID * TPB) {
        g_hbd[i] = 0.f; g_hb1[i] = 0.f; g_hb2[i] = 0.f;
    }
    for (int r = bid * 2 + half; r < F; r += GRID * 2) {
        if (r < N) {
            float acc = node_b[t2];
#pragma unroll
            for (int k = 0; k < 4; k++) acc = fmaf(x[r * 4 + k], node_w[k * HD + t2], acc);
            g_h[r * HD + t2] = acc;
            g_agg[r * HD + t2] = 0.f;
            if (t2 < HEADS) g_den[r * HEADS + t2] = 0.f;
        } else {
            int e = r - N;
            float acc = edgep_b[t2];
#pragma unroll
            for (int k = 0; k < 5; k++) acc = fmaf(ea[e * 5 + k], edgep_w[k * HD + t2], acc);
            g_e[e * HD + t2] = acc;
        }
    }
    gridbar(&s_gen);

    int nb_n = (N + 3) >> 2, nb_e = (E + 3) >> 2;
    int ng = nb_n + nb_e;
    int itersA = (ng + GRID * 2 - 1) / (GRID * 2);
    int itersC = (N + GRID * 2 - 1) / (GRID * 2);

    for (int l = 0; l < NLAYER; l++) {
        const float* Wn   = gat_lin + l * HD * HD;
        const float* We   = gat_le  + l * HD * HD;
        const float* asrc = att_src + l * HEADS * CDIM;
        const float* adst = att_dst + l * HEADS * CDIM;
        const float* aedg = att_ed  + l * HEADS * CDIM;

        // ---- phase A: projections + attention dot products ----------------
        for (int it = 0; it < itersA; it++) {
            int g = bid * 2 + half + it * GRID * 2;
            bool valid = g < ng;
            bool isnode = valid && (g < nb_n);
            int r0 = 0, cnt = 0;
            const float* basep = g_h;
            const float* W = Wn;
            if (valid) {
                r0 = (isnode ? g : g - nb_n) * 4;
                cnt = (isnode ? N : E) - r0; if (cnt > 4) cnt = 4;
                if (!isnode) { basep = g_e; W = We; }
            }
#pragma unroll
            for (int rr = 0; rr < 4; rr++)
                rows[half][rr][t2] = (rr < cnt) ? basep[(size_t)(r0 + rr) * HD + t2] : 0.f;
            __syncthreads();
            float a0 = 0.f, a1 = 0.f, a2 = 0.f, a3 = 0.f;
            if (valid) {
#pragma unroll 4
                for (int k = 0; k < HD; k++) {
                    float wv = W[k * HD + t2];
                    a0 = fmaf(rows[half][0][k], wv, a0);
                    a1 = fmaf(rows[half][1][k], wv, a1);
                    a2 = fmaf(rows[half][2][k], wv, a2);
                    a3 = fmaf(rows[half][3][k], wv, a3);
                }
            }
            outs[half][0][t2] = a0; outs[half][1][t2] = a1;
            outs[half][2][t2] = a2; outs[half][3][t2] = a3;
            if (isnode) {
                if (0 < cnt) g_xl[(size_t)(r0 + 0) * HD + t2] = a0;
                if (1 < cnt) g_xl[(size_t)(r0 + 1) * HD + t2] = a1;
                if (2 < cnt) g_xl[(size_t)(r0 + 2) * HD + t2] = a2;
                if (3 < cnt) g_xl[(size_t)(r0 + 3) * HD + t2] = a3;
            }
            __syncthreads();
            if (w2 < cnt) {
                if (isnode) {
#pragma unroll
                    for (int h = 0; h < HEADS; h++) {
                        float xv = outs[half][w2][h * 32 + lane];
                        float vs = xv * asrc[h * 32 + lane];
                        float vd = xv * adst[h * 32 + lane];
#pragma unroll
                        for (int o = 16; o > 0; o >>= 1) {
                            vs += __shfl_down_sync(0xffffffffu, vs, o);
                            vd += __shfl_down_sync(0xffffffffu, vd, o);
                        }
                        if (lane == 0) {
                            g_ssrc[(r0 + w2) * HEADS + h] = vs;
                            g_sdst[(r0 + w2) * HEADS + h] = vd;
                        }
                    }
                } else {
#pragma unroll
                    for (int h = 0; h < HEADS; h++) {
                        float v = outs[half][w2][h * 32 + lane] * aedg[h * 32 + lane];
#pragma unroll
                        for (int o = 16; o > 0; o >>= 1)
                            v += __shfl_down_sync(0xffffffffu, v, o);
                        if (lane == 0) {
                            g_ae[(r0 + w2) * HEADS + h] = v;
                            atomicAdd(&g_aesum[h], v);
                        }
                    }
                }
            }
            __syncthreads();
        }
        gridbar(&s_gen);

        // ---- phase B: edge aggregation (unnormalized softmax) -------------
        for (int f = bid * 2 + half; f < F; f += GRID * 2) {
            int s, d; float ae;
            if (f < E) { s = src[f]; d = dst[f]; ae = g_ae[f * HEADS + w2]; }
            else       { s = f - E; d = s;       ae = g_aesum[w2] / (float)E; }
            float a = g_ssrc[s * HEADS + w2] + g_sdst[d * HEADS + w2] + ae;
            a = a > 0.f ? a : 0.2f * a;
            float ex = expf(a);
            atomicAdd(&g_agg[d * HD + t2], g_xl[(size_t)s * HD + t2] * ex);
            if (lane == 0) atomicAdd(&g_den[d * HEADS + w2], ex);
        }
        gridbar(&s_gen);

        // ---- phase C: layernorm(relu(agg/den + bias) + h) ------------------
        const float* bias = gat_b + l * HD;
        const float* lns  = ln_s + l * HD;
        const float* lnb  = ln_b + l * HD;
        for (int it = 0; it < itersC; it++) {
            int n = bid * 2 + half + it * GRID * 2;
            bool valid = n < N;
            float v = 0.f;
            if (valid) {
                float den = g_den[n * HEADS + w2];
                v = g_agg[n * HD + t2] / den + bias[t2];
                g_agg[n * HD + t2] = 0.f;
                if (t2 < HEADS) g_den[n * HEADS + t2] = 0.f;
                v = v > 0.f ? v : 0.f;
                v += g_h[n * HD + t2];
            }
            float s1 = v;
#pragma unroll
            for (int o = 16; o > 0; o >>= 1) s1 += __shfl_down_sync(0xffffffffu, s1, o);
            if (lane == 0) redh[half][w2] = s1;
            __syncthreads();
            float mu = (redh[half][0] + redh[half][1] + redh[half][2] + redh[half][3]) * (1.f / HD);
            float dd = valid ? v - mu : 0.f;
            float s2 = dd * dd;
#pragma unroll
            for (int o = 16; o > 0; o >>= 1) s2 += __shfl_down_sync(0xffffffffu, s2, o);
            if (lane == 0) redv[half][w2] = s2;
            __syncthreads();
            float var = (redv[half][0] + redv[half][1] + redv[half][2] + redv[half][3]) * (1.f / HD);
            if (valid)
                g_h[n * HD + t2] = dd * rsqrtf(var + 1e-5f) * lns[t2] + lnb[t2];
            __syncthreads();
        }
        if (gtid < HEADS) g_aesum[gtid] = 0.f;
        gridbar(&s_gen);
    }

    // ---- phase D: MLPs (295 CTAs, one row per warp)  ||  dna scan (last CTA)
    if (bid == GRID - 1) {
        for (int n = tid; n < N; n += TPB) {
            float a = x[n * 4], b = x[n * 4 + 1], c = x[n * 4 + 2], d = x[n * 4 + 3];
            int dna = (a != 0.f || b != 0.f || c != 0.f || d != 0.f) ? 1 : 0;
            smi[n] = dna;
            g_dna[n] = dna;
            sbt[n] = batch[n];
        }
        __syncthreads();
        if (tid == 0) {
            int cum = 0, curb = -1, gstart = 0;
            for (int n = 0; n < N; n++) {
                int b = sbt[n];
                if (b != curb) { curb = b; gstart = cum; }
                slo[n] = cum - gstart;
                cum += smi[n];
            }
        }
        __syncthreads();
        for (int n = tid; n < N; n += TPB) g_loc[n] = slo[n];
    } else {
        int wl = tid >> 5, lane32 = tid & 31;
        int wg = bid * 8 + wl;
        float* rb = rowbuf[wl];
        for (int row = wg; row < F; row += (GRID - 1) * 8) {
            const float* rowp = (row < N) ? (g_h + (size_t)row * HD)
                                          : (g_e + (size_t)(row - N) * HD);
            rb[lane32]      = rowp[lane32];
            rb[lane32 + 32] = rowp[lane32 + 32];
            rb[lane32 + 64] = rowp[lane32 + 64];
            rb[lane32 + 96] = rowp[lane32 + 96];
            __syncwarp();
            const float* W1 = (row < N) ? on_w1 : cp_w1;
            const float* B1 = (row < N) ? on_b1 : cp_b1;
            const float* W2 = (row < N) ? on_w2 : cp_w2;
            const float* B2 = (row < N) ? on_b2 : cp_b2;
            float o = 0.f;
#pragma unroll
            for (int c2 = 0; c2 < 2; c2++) {
                int c = lane32 + 32 * c2;
                float acc = B1[c];
#pragma unroll 8
                for (int k = 0; k < HD; k++) acc = fmaf(rb[k], W1[k * 64 + c], acc);
                acc = acc > 0.f ? acc : 0.f;
                o = fmaf(acc, W2[c], o);
            }
#pragma unroll
            for (int off = 16; off > 0; off >>= 1)
                o += __shfl_down_sync(0xffffffffu, o, off);
            if (lane32 == 0) {
                float val = o + B2[0];
                if (row < N) g_onsite[row] = val; else g_coup[row - N] = val;
            }
            __syncwarp();
        }
    }
    gridbar(&s_gen);

    // ---- phase E: band assembly ------------------------------------------
    int tot = F + B * HS;
    for (int idx = gtid; idx < tot; idx += GRID * TPB) {
        if (idx < N) {
            if (g_dna[idx])
                atomicAdd(&g_hbd[batch[idx] * HS + g_loc[idx]], g_onsite[idx]);
        } else if (idx < F) {
            int e = idx - N;
            int s = src[e], d = dst[e];
            if (g_dna[s] && g_dna[d]) {
                int b = batch[s], u = g_loc[s], v = g_loc[d];
                int lo = u < v ? u : v;
                int bd = u < v ? v - u : u - v;
                float cv = g_coup[e];
                if (bd == 1)      atomicAdd(&g_hb1[b * HS + lo], cv);
                else if (bd == 2) atomicAdd(&g_hb2[b * HS + lo], cv);
            }
        } else {
            int i = idx - F;
            g_dvb[i] = 0.5f * (GL[i] + GR[i]) + 1e-12f;
        }
    }
    gridbar(&s_gen);

    // ---- phase F: banded LU, one thread per (b,e) --------------------------
    for (int be = gtid; be < BE; be += GRID * TPB) {
        int b = be / NEG, e = be % NEG;
        float Eg = (float)(-3.0 + 6.0 * (double)e / 99.0);
        const float* hd = g_hbd + b * HS;
        const float* h1 = g_hb1 + b * HS;
        const float* h2 = g_hb2 + b * HS;
        const float* dv = g_dvb + b * HS;
        float2* out = g_lu + (size_t)be * 5 * HS;
        g_Tacc[be] = 0.f; g_Dacc[be] = 0.f; g_cnt[be] = 0;

        float2 e1 = {0.f, 0.f}, e2 = {0.f, 0.f};
        float2 f1 = {0.f, 0.f}, f2 = {0.f, 0.f};
        float2 di1 = {0.f, 0.f}, di2 = {0.f, 0.f};
        for (int i = 0; i < HS; i++) {
            float2 Mi = make_float2(Eg - (hd[i] + 1e-6f), dv[i]);
            float m1 = (i >= 1) ? -h1[i - 1] : 0.f;
            float m2 = (i >= 2) ? -h2[i - 2] : 0.f;
            float2 bi = make_float2(m2 * di2.x, m2 * di2.y);
            float2 tt = make_float2(m1, 0.f);
            CFMS(tt, bi, e2);
            float2 ai; CMUL(ai, tt, di1);
            float2 d = Mi;
            CFMS(d, bi, f2);
            CFMS(d, ai, e1);
            float2 ei = make_float2(0.f, 0.f);
            if (i < HS - 1) { ei = make_float2(-h1[i], 0.f); CFMS(ei, ai, f1); }
            float2 fi = make_float2((i < HS - 2) ? -h2[i] : 0.f, 0.f);
            float inv = 1.f / fmaf(d.x, d.x, d.y * d.y);
            float2 dinv = make_float2(d.x * inv, -d.y * inv);
            out[0 * HS + i] = ai;
            out[1 * HS + i] = bi;
            out[2 * HS + i] = ei;
            out[3 * HS + i] = fi;
            out[4 * HS + i] = dinv;
            e2 = e1; e1 = ei; f2 = f1; f1 = fi; di2 = di1; di1 = dinv;
        }
    }
}

// ---------------- solve kernel (also writes dense H output) ----------------
__global__ void __launch_bounds__(32) k_solve(
    const float* __restrict__ GL, const float* __restrict__ GR,
    float* __restrict__ Tout, float* __restrict__ Dout,
    float* __restrict__ Hout, int BE, int B) {
    __shared__ float2 ys[HS * 32];
    __shared__ float2 sa[HS], sb[HS], se[HS], sf[HS], sdi[HS];
    __shared__ float  sgl[HS], sgr[HS];
    int blk = blockIdx.x;
    int be = blk >> 2, q = blk & 3;
    int b = be / NEG;
    int lane = threadIdx.x;

    // write this block's chunk of the dense H output (from bands)
    {
        int tot = B * HS * HS;
        int nblk = gridDim.x;
        int per = (tot + nblk - 1) / nblk;
        int start = blk * per;
        int end = start + per; if (end > tot) end = tot;
        for (int idx = start + lane; idx < end; idx += 32) {
            int bb = idx / (HS * HS);
            int r = (idx % (HS * HS)) / HS, c = idx % HS;
            int lo = r < c ? r : c;
            int bd = r < c ? c - r : r - c;
            float v;
            if (bd == 0)      v = g_hbd[bb * HS + r] + 1e-6f;
            else if (bd == 1) v = g_hb1[bb * HS + lo];
            else if (bd == 2) v = g_hb2[bb * HS + lo];
            else              v = 0.f;
            Hout[idx] = v;
        }
    }

    const float2* lu = g_lu + (size_t)be * 5 * HS;
#pragma unroll
    for (int k = 0; k < 4; k++) {
        int i = lane + k * 32;
        sa[i]  = lu[0 * HS + i];
        sb[i]  = lu[1 * HS + i];
        se[i]  = lu[2 * HS + i];
        sf[i]  = lu[3 * HS + i];
        sdi[i] = lu[4 * HS + i];
        sgl[i] = GL[b * HS + i];
        sgr[i] = GR[b * HS + i];
    }
    __syncwarp();

    int j = q * 32 + lane;
    int i0 = q * 32;
    float2 y1 = {0.f, 0.f}, y2 = {0.f, 0.f};
    for (int i = i0; i < HS; i++) {
        float2 y = make_float2((i == j) ? 1.f : 0.f, 0.f);
        CFMS(y, sa[i], y1);
        CFMS(y, sb[i], y2);
        ys[i * 32 + lane] = y;
        y2 = y1; y1 = y;
    }
    float2 x1 = {0.f, 0.f}, x2 = {0.f, 0.f};
    float tp = 0.f, dj = 0.f;
    for (int i = HS - 1; i >= 0; i--) {
        float2 t = (i >= i0) ? ys[i * 32 + lane] : make_float2(0.f, 0.f);
        CFMS(t, se[i], x1);
        CFMS(t, sf[i], x2);
        float2 xx; CMUL(xx, t, sdi[i]);
        tp = fmaf(sgl[i], fmaf(xx.x, xx.x, xx.y * xx.y), tp);
        if (i == j) dj = xx.y;
        x2 = x1; x1 = xx;
    }
    tp *= sgr[j];
#pragma unroll
    for (int o = 16; o > 0; o >>= 1) {
        tp += __shfl_down_sync(0xffffffffu, tp, o);
        dj += __shfl_down_sync(0xffffffffu, dj, o);
    }
    if (lane == 0) {
        atomicAdd(&g_Tacc[be], tp);
        atomicAdd(&g_Dacc[be], dj);
        __threadfence();
        int old = atomicAdd(&g_cnt[be], 1);
        if (old == 3) {
            __threadfence();
            Tout[be] = log10f(fmaxf(g_Tacc[be], 1e-16f));
            Dout[be] = log10f(fmaxf(-g_Dacc[be] / 3.14159265358979323846f, 1e-16f));
        }
    }
}

// ---------------- launch ----------------------------------------------------
extern "C" void kernel_launch(void* const* d_in, const int* in_sizes, int n_in,
                              void* d_out, int out_size) {
    const float* x      = (const float*)d_in[0];
    const int*   ei     = (const int*)  d_in[1];
    const float* ea     = (const float*)d_in[2];
    const int*   batch  = (const int*)  d_in[3];
    const float* GL     = (const float*)d_in[4];
    const float* GR     = (const float*)d_in[5];
    const float* node_w = (const float*)d_in[6];
    const float* node_b = (const float*)d_in[7];
    const float* edgep_w= (const float*)d_in[8];
    const float* edgep_b= (const float*)d_in[9];
    const float* gat_lin= (const float*)d_in[10];
    const float* att_src= (const float*)d_in[11];
    const float* att_dst= (const float*)d_in[12];
    const float* gat_le = (const float*)d_in[13];
    const float* att_ed = (const float*)d_in[14];
    const float* gat_b  = (const float*)d_in[15];
    const float* ln_s   = (const float*)d_in[16];
    const float* ln_b   = (const float*)d_in[17];
    const float* on_w1  = (const float*)d_in[18];
    const float* on_b1  = (const float*)d_in[19];
    const float* on_w2  = (const float*)d_in[20];
    const float* on_b2  = (const float*)d_in[21];
    const float* cp_w1  = (const float*)d_in[22];
    const float* cp_b1  = (const float*)d_in[23];
    const float* cp_w2  = (const float*)d_in[24];
    const float* cp_b2  = (const float*)d_in[25];

    int N = in_sizes[0] / 4;
    int E = in_sizes[2] / 5;
    int B = in_sizes[4] / HS;
    int BE = B * NEG;
    const int* src = ei;
    const int* dst = ei + E;

    float* out  = (float*)d_out;
    float* Tout = out;
    float* Dout = out + BE;
    float* Hout = out + 2 * BE;

    k_pers<<<GRID, TPB>>>(x, src, dst, ea, batch, GL, GR,
                          node_w, node_b, edgep_w, edgep_b,
                          gat_lin, att_src, att_dst, gat_le, att_ed,
                          gat_b, ln_s, ln_b,
                          on_w1, on_b1, on_w2, on_b2,
                          cp_w1, cp_b1, cp_w2, cp_b2, N, E, B);
    k_solve<<<BE * 4, 32>>>(GL, GR, Tout, Dout, Hout, BE, B);
}

// round 10
// speedup vs baseline: 1.2104x; 1.2104x over previous
#include <cuda_runtime.h>
#include <math.h>

#define HD     128
#define HEADS  4
#define CDIM   32
#define NLAYER 4
#define NEG    100
#define HS     128

#define N_MAX  2048
#define E_MAX  4096
#define B_MAX  32
#define BE_MAX (B_MAX * NEG)

// ---------------- scratch (device globals; no allocation allowed) ----------
__device__ float g_h   [N_MAX * HD];
__device__ float g_e   [E_MAX * HD];
__device__ float g_xl  [N_MAX * HD];
__device__ float g_ssrc[N_MAX * HEADS];
__device__ float g_sdst[N_MAX * HEADS];
__device__ float g_ae  [E_MAX * HEADS];
__device__ float g_aesum[HEADS];
__device__ float g_den  [N_MAX * HEADS];
__device__ float g_agg  [N_MAX * HD];
__device__ float g_onsite[N_MAX];
__device__ float g_coup  [E_MAX];
__device__ int   g_dna  [N_MAX];
__device__ int   g_loc  [N_MAX];
// NEGF scratch
__device__ float g_hbd[B_MAX * HS];
__device__ float g_hb1[B_MAX * HS];
__device__ float g_hb2[B_MAX * HS];
__device__ float g_dvb[B_MAX * HS];
__device__ float2 g_lu[BE_MAX * 5 * HS];
__device__ float g_Tacc[BE_MAX];
__device__ float g_Dacc[BE_MAX];
__device__ int   g_cnt [BE_MAX];

// complex mul / fms helpers
#define CMUL(o, a, b) do { \
    (o).x = (a).x * (b).x - (a).y * (b).y; \
    (o).y = (a).x * (b).y + (a).y * (b).x; \
} while (0)
#define CFMS(m, c, r) do { \
    (m).x = fmaf(-(c).x, (r).x, fmaf((c).y, (r).y, (m).x)); \
    (m).y = fmaf(-(c).x, (r).y, fmaf(-(c).y, (r).x, (m).y)); \
} while (0)

// ---------------- GNN kernels ----------------------------------------------
// merged node+edge input projections (one launch)
__global__ void k_init(const float* __restrict__ x, const float* __restrict__ ea,
                       const float* __restrict__ nw, const float* __restrict__ nb,
                       const float* __restrict__ ew, const float* __restrict__ eb,
                       int N) {
    int r = blockIdx.x, t = threadIdx.x;
    if (r < N) {
        float acc = nb[t];
#pragma unroll
        for (int k = 0; k < 4; k++) acc = fmaf(x[r * 4 + k], nw[k * HD + t], acc);
        g_h[r * HD + t] = acc;
        g_agg[r * HD + t] = 0.f;
        if (t < HEADS) g_den[r * HEADS + t] = 0.f;
        if (r == 0 && t < HEADS) g_aesum[t] = 0.f;
    } else {
        int e = r - N;
        float acc = eb[t];
#pragma unroll
        for (int k = 0; k < 5; k++) acc = fmaf(ea[e * 5 + k], ew[k * HD + t], acc);
        g_e[e * HD + t] = acc;
    }
}

// fused xl (nodes) + edge-attention projection: 8 rows per block
__global__ void k_attn(const float* __restrict__ Wn, const float* __restrict__ asrc,
                       const float* __restrict__ adst, const float* __restrict__ We,
                       const float* __restrict__ aedge, int N, int E, int nb_n) {
    __shared__ float rows[8][HD];
    __shared__ float outs[8][HD];
    int t = threadIdx.x;
    bool isnode = (blockIdx.x < nb_n);
    int r0 = (isnode ? blockIdx.x : blockIdx.x - nb_n) * 8;
    int cnt = (isnode ? N : E) - r0; if (cnt > 8) cnt = 8;
    const float* base = isnode ? g_h : g_e;
    const float* W = isnode ? Wn : We;
#pragma unroll
    for (int rr = 0; rr < 8; rr++)
        rows[rr][t] = (rr < cnt) ? base[(size_t)(r0 + rr) * HD + t] : 0.f;
    __syncthreads();
    float a[8];
#pragma unroll
    for (int rr = 0; rr < 8; rr++) a[rr] = 0.f;
#pragma unroll 4
    for (int k = 0; k < HD; k++) {
        float wv = W[k * HD + t];
#pragma unroll
        for (int rr = 0; rr < 8; rr++) a[rr] = fmaf(rows[rr][k], wv, a[rr]);
    }
#pragma unroll
    for (int rr = 0; rr < 8; rr++) outs[rr][t] = a[rr];
    if (isnode) {
#pragma unroll
        for (int rr = 0; rr < 8; rr++)
            if (rr < cnt) g_xl[(size_t)(r0 + rr) * HD + t] = a[rr];
    }
    __syncthreads();
    int w = t >> 5, lane = t & 31;
#pragma unroll
    for (int rsel = 0; rsel < 2; rsel++) {
        int rr = w + rsel * 4;
        if (rr < cnt) {
            if (isnode) {
#pragma unroll
                for (int h = 0; h < HEADS; h++) {
                    float xv = outs[rr][h * 32 + lane];
                    float vs = xv * asrc[h * 32 + lane];
                    float vd = xv * adst[h * 32 + lane];
#pragma unroll
                    for (int o = 16; o > 0; o >>= 1) {
                        vs += __shfl_down_sync(0xffffffffu, vs, o);
                        vd += __shfl_down_sync(0xffffffffu, vd, o);
                    }
                    if (lane == 0) {
                        g_ssrc[(r0 + rr) * HEADS + h] = vs;
                        g_sdst[(r0 + rr) * HEADS + h] = vd;
                    }
                }
            } else {
#pragma unroll
                for (int h = 0; h < HEADS; h++) {
                    float v = outs[rr][h * 32 + lane] * aedge[h * 32 + lane];
#pragma unroll
                    for (int o = 16; o > 0; o >>= 1)
                        v += __shfl_down_sync(0xffffffffu, v, o);
                    if (lane == 0) {
                        g_ae[(r0 + rr) * HEADS + h] = v;
                        atomicAdd(&g_aesum[h], v);
                    }
                }
            }
        }
    }
}

// fused attention-weight + aggregation (softmax shift cancels exactly)
__global__ void k_edgeagg(const int* __restrict__ src, const int* __restrict__ dst,
                          int N, int E) {
    int f = blockIdx.x, t = threadIdx.x;
    int hh = t >> 5, lane = t & 31;
    int s, d; float ae;
    if (f < E) { s = src[f]; d = dst[f]; ae = g_ae[f * HEADS + hh]; }
    else       { s = f - E; d = s;       ae = g_aesum[hh] / (float)E; }
    float a = g_ssrc[s * HEADS + hh] + g_sdst[d * HEADS + hh] + ae;
    a = a > 0.f ? a : 0.2f * a;
    float ex = expf(a);
    atomicAdd(&g_agg[d * HD + t], g_xl[(size_t)s * HD + t] * ex);
    if (lane == 0) atomicAdd(&g_den[d * HEADS + hh], ex);
}

// layernorm(relu(agg/den + bias) + h); zero accumulators for the next layer
__global__ void k_ln(const float* __restrict__ bias, const float* __restrict__ s,
                     const float* __restrict__ bb) {
    __shared__ float redh[4], redv[4];
    int n = blockIdx.x, t = threadIdx.x;
    int w = t >> 5, lane = t & 31;
    float den = g_den[n * HEADS + w];
    float v = g_agg[n * HD + t] / den + bias[t];
    g_agg[n * HD + t] = 0.f;
    if (t < HEADS) g_den[n * HEADS + t] = 0.f;
    v = v > 0.f ? v : 0.f;
    v += g_h[n * HD + t];
    float s1 = v;
#pragma unroll
    for (int o = 16; o > 0; o >>= 1) s1 += __shfl_down_sync(0xffffffffu, s1, o);
    if (lane == 0) redh[w] = s1;
    __syncthreads();
    float mu = (redh[0] + redh[1] + redh[2] + redh[3]) * (1.f / HD);
    float dd = v - mu;
    float s2 = dd * dd;
#pragma unroll
    for (int o = 16; o > 0; o >>= 1) s2 += __shfl_down_sync(0xffffffffu, s2, o);
    if (lane == 0) redv[w] = s2;
    __syncthreads();
    float var = (redv[0] + redv[1] + redv[2] + redv[3]) * (1.f / HD);
    g_h[n * HD + t] = dd * rsqrtf(var + 1e-5f) * s[t] + bb[t];
    if (n == 0 && t < HEADS) g_aesum[t] = 0.f;
}

// onsite/coupling MLPs, 8 rows per block (64 threads)
__global__ void k_mlp(const float* __restrict__ w1, const float* __restrict__ b1,
                      const float* __restrict__ w2, const float* __restrict__ b2,
                      const float* __restrict__ cw1, const float* __restrict__ cb1,
                      const float* __restrict__ cw2, const float* __restrict__ cb2,
                      int N, int E, int nb_n) {
    __shared__ float rows[8][HD];
    __shared__ float red[8][2];
    int t = threadIdx.x;
    bool isnode = (blockIdx.x < nb_n);
    int r0 = (isnode ? blockIdx.x : blockIdx.x - nb_n) * 8;
    int cnt = (isnode ? N : E) - r0; if (cnt > 8) cnt = 8;
    const float* base = isnode ? g_h : g_e;
    const float* W1 = isnode ? w1 : cw1;
    const float* B1 = isnode ? b1 : cb1;
    const float* W2 = isnode ? w2 : cw2;
    const float* B2 = isnode ? b2 : cb2;
#pragma unroll
    for (int rr = 0; rr < 8; rr++) {
        float v0 = 0.f, v1 = 0.f;
        if (rr < cnt) {
            v0 = base[(size_t)(r0 + rr) * HD + t];
            v1 = base[(size_t)(r0 + rr) * HD + t + 64];
        }
        rows[rr][t] = v0; rows[rr][t + 64] = v1;
    }
    __syncthreads();
    float acc[8];
    float b1v = B1[t];
#pragma unroll
    for (int rr = 0; rr < 8; rr++) acc[rr] = b1v;
#pragma unroll 4
    for (int k = 0; k < HD; k++) {
        float wv = W1[k * 64 + t];
#pragma unroll
        for (int rr = 0; rr < 8; rr++) acc[rr] = fmaf(rows[rr][k], wv, acc[rr]);
    }
    float w2v = W2[t];
    int w = t >> 5, lane = t & 31;
#pragma unroll
    for (int rr = 0; rr < 8; rr++) {
        float p = (acc[rr] > 0.f ? acc[rr] : 0.f) * w2v;
#pragma unroll
        for (int o = 16; o > 0; o >>= 1) p += __shfl_down_sync(0xffffffffu, p, o);
        if (lane == 0) red[rr][w] = p;
    }
    __syncthreads();
    if (t < 8 && t < cnt) {
        float val = red[t][0] + red[t][1] + B2[0];
        int row = r0 + t;
        if (isnode) g_onsite[row] = val; else g_coup[row] = val;
    }
}

// dna mask + local index: warp-per-graph ballot scan (graphs contiguous,
// uniform size N/B -- same construction guarantee as the band structure)
__global__ void k_dna(const float* __restrict__ x, int N, int B) {
    int t = threadIdx.x;
    for (int i = t; i < B * HS; i += blockDim.x) {
        g_hbd[i] = 0.f; g_hb1[i] = 0.f; g_hb2[i] = 0.f;
    }
    int warp = t >> 5, lane = t & 31;
    int npg = N / B;
    if (warp < B) {
        int base = warp * npg;
        int off = 0;
        for (int c = 0; c < npg; c += 32) {
            int li = c + lane;
            int mi = 0;
            if (li < npg) {
                int n = base + li;
                float a = x[n * 4], b = x[n * 4 + 1], cc = x[n * 4 + 2], d = x[n * 4 + 3];
                mi = (a != 0.f || b != 0.f || cc != 0.f || d != 0.f) ? 1 : 0;
                g_dna[n] = mi;
            }
            unsigned bits = __ballot_sync(0xffffffffu, mi);
            if (li < npg) g_loc[base + li] = off + __popc(bits & ((1u << lane) - 1u));
            off += __popc(bits);
        }
    }
}

// assemble bands: onsite->diag, coup->band1/band2, dvb from GL/GR
__global__ void k_basm(const int* __restrict__ src, const int* __restrict__ dst,
                       const int* __restrict__ batch,
                       const float* __restrict__ GL, const float* __restrict__ GR,
                       int N, int E, int B) {
    int idx = blockIdx.x * blockDim.x + threadIdx.x;
    if (idx < N) {
        if (g_dna[idx])
            atomicAdd(&g_hbd[batch[idx] * HS + g_loc[idx]], g_onsite[idx]);
    } else if (idx < N + E) {
        int e = idx - N;
        int s = src[e], d = dst[e];
        if (g_dna[s] && g_dna[d]) {
            int b = batch[s], u = g_loc[s], v = g_loc[d];
            int lo = u < v ? u : v;
            int bd = u < v ? v - u : u - v;
            float cv = g_coup[e];
            if (bd == 1)      atomicAdd(&g_hb1[b * HS + lo], cv);
            else if (bd == 2) atomicAdd(&g_hb2[b * HS + lo], cv);
        }
    } else if (idx < N + E + B * HS) {
        int i = idx - N - E;
        g_dvb[i] = 0.5f * (GL[i] + GR[i]) + 1e-12f;
    }
}

// banded LU (one thread per (b,e)) + dense H output write (grid-stride)
__global__ void k_lu(float* __restrict__ Hout, int BE, int B) {
    int gtid = blockIdx.x * blockDim.x + threadIdx.x;
    int nthr = gridDim.x * blockDim.x;

    // dense H (output) from bands
    int tot = B * HS * HS;
    for (int idx = gtid; idx < tot; idx += nthr) {
        int bb = idx / (HS * HS);
        int r = (idx % (HS * HS)) / HS, c = idx % HS;
        int lo = r < c ? r : c;
        int bd = r < c ? c - r : r - c;
        float v;
        if (bd == 0)      v = g_hbd[bb * HS + r] + 1e-6f;
        else if (bd == 1) v = g_hb1[bb * HS + lo];
        else if (bd == 2) v = g_hb2[bb * HS + lo];
        else              v = 0.f;
        Hout[idx] = v;
    }

    for (int be = gtid; be < BE; be += nthr) {
        int b = be / NEG, e = be % NEG;
        float Eg = (float)(-3.0 + 6.0 * (double)e / 99.0);
        const float* hd = g_hbd + b * HS;
        const float* h1 = g_hb1 + b * HS;
        const float* h2 = g_hb2 + b * HS;
        const float* dv = g_dvb + b * HS;
        float2* out = g_lu + (size_t)be * 5 * HS;
        g_Tacc[be] = 0.f; g_Dacc[be] = 0.f; g_cnt[be] = 0;

        float2 e1 = {0.f, 0.f}, e2 = {0.f, 0.f};
        float2 f1 = {0.f, 0.f}, f2 = {0.f, 0.f};
        float2 di1 = {0.f, 0.f}, di2 = {0.f, 0.f};
        for (int i = 0; i < HS; i++) {
            float2 Mi = make_float2(Eg - (hd[i] + 1e-6f), dv[i]);
            float m1 = (i >= 1) ? -h1[i - 1] : 0.f;
            float m2 = (i >= 2) ? -h2[i - 2] : 0.f;
            float2 bi = make_float2(m2 * di2.x, m2 * di2.y);
            float2 tt = make_float2(m1, 0.f);
            CFMS(tt, bi, e2);
            float2 ai; CMUL(ai, tt, di1);
            float2 d = Mi;
            CFMS(d, bi, f2);
            CFMS(d, ai, e1);
            float2 ei = make_float2(0.f, 0.f);
            if (i < HS - 1) { ei = make_float2(-h1[i], 0.f); CFMS(ei, ai, f1); }
            float2 fi = make_float2((i < HS - 2) ? -h2[i] : 0.f, 0.f);
            float inv = 1.f / fmaf(d.x, d.x, d.y * d.y);
            float2 dinv = make_float2(d.x * inv, -d.y * inv);
            out[0 * HS + i] = ai;
            out[1 * HS + i] = bi;
            out[2 * HS + i] = ei;
            out[3 * HS + i] = fi;
            out[4 * HS + i] = dinv;
            e2 = e1; e1 = ei; f2 = f1; f1 = fi; di2 = di1; di1 = dinv;
        }
    }
}

// column solves: one warp-CTA per (b,e, quarter); lane = column j.
// Last CTA per (b,e) writes the final log10 outputs.
__global__ void __launch_bounds__(32) k_solve(
    const float* __restrict__ GL, const float* __restrict__ GR,
    float* __restrict__ Tout, float* __restrict__ Dout, int BE) {
    __shared__ float2 ys[HS * 32];
    __shared__ float2 sa[HS], sb[HS], se[HS], sf[HS], sdi[HS];
    __shared__ float  sgl[HS], sgr[HS];
    int blk = blockIdx.x;
    int be = blk >> 2, q = blk & 3;
    int b = be / NEG;
    int lane = threadIdx.x;
    const float2* lu = g_lu + (size_t)be * 5 * HS;
#pragma unroll
    for (int k = 0; k < 4; k++) {
        int i = lane + k * 32;
        sa[i]  = lu[0 * HS + i];
        sb[i]  = lu[1 * HS + i];
        se[i]  = lu[2 * HS + i];
        sf[i]  = lu[3 * HS + i];
        sdi[i] = lu[4 * HS + i];
        sgl[i] = GL[b * HS + i];
        sgr[i] = GR[b * HS + i];
    }
    __syncwarp();

    int j = q * 32 + lane;
    int i0 = q * 32;
    float2 y1 = {0.f, 0.f}, y2 = {0.f, 0.f};
    for (int i = i0; i < HS; i++) {
        float2 y = make_float2((i == j) ? 1.f : 0.f, 0.f);
        CFMS(y, sa[i], y1);
        CFMS(y, sb[i], y2);
        ys[i * 32 + lane] = y;
        y2 = y1; y1 = y;
    }
    float2 x1 = {0.f, 0.f}, x2 = {0.f, 0.f};
    float tp = 0.f, dj = 0.f;
    for (int i = HS - 1; i >= 0; i--) {
        float2 t = (i >= i0) ? ys[i * 32 + lane] : make_float2(0.f, 0.f);
        CFMS(t, se[i], x1);
        CFMS(t, sf[i], x2);
        float2 xx; CMUL(xx, t, sdi[i]);
        tp = fmaf(sgl[i], fmaf(xx.x, xx.x, xx.y * xx.y), tp);
        if (i == j) dj = xx.y;
        x2 = x1; x1 = xx;
    }
    tp *= sgr[j];
#pragma unroll
    for (int o = 16; o > 0; o >>= 1) {
        tp += __shfl_down_sync(0xffffffffu, tp, o);
        dj += __shfl_down_sync(0xffffffffu, dj, o);
    }
    if (lane == 0) {
        atomicAdd(&g_Tacc[be], tp);
        atomicAdd(&g_Dacc[be], dj);
        __threadfence();
        int old = atomicAdd(&g_cnt[be], 1);
        if (old == 3) {
            __threadfence();
            Tout[be] = log10f(fmaxf(g_Tacc[be], 1e-16f));
            Dout[be] = log10f(fmaxf(-g_Dacc[be] / 3.14159265358979323846f, 1e-16f));
        }
    }
}

// ---------------- launch ----------------------------------------------------
extern "C" void kernel_launch(void* const* d_in, const int* in_sizes, int n_in,
                              void* d_out, int out_size) {
    const float* x      = (const float*)d_in[0];
    const int*   ei     = (const int*)  d_in[1];
    const float* ea     = (const float*)d_in[2];
    const int*   batch  = (const int*)  d_in[3];
    const float* GL     = (const float*)d_in[4];
    const float* GR     = (const float*)d_in[5];
    const float* node_w = (const float*)d_in[6];
    const float* node_b = (const float*)d_in[7];
    const float* edgep_w= (const float*)d_in[8];
    const float* edgep_b= (const float*)d_in[9];
    const float* gat_lin= (const float*)d_in[10];
    const float* att_src= (const float*)d_in[11];
    const float* att_dst= (const float*)d_in[12];
    const float* gat_le = (const float*)d_in[13];
    const float* att_ed = (const float*)d_in[14];
    const float* gat_b  = (const float*)d_in[15];
    const float* ln_s   = (const float*)d_in[16];
    const float* ln_b   = (const float*)d_in[17];
    const float* on_w1  = (const float*)d_in[18];
    const float* on_b1  = (const float*)d_in[19];
    const float* on_w2  = (const float*)d_in[20];
    const float* on_b2  = (const float*)d_in[21];
    const float* cp_w1  = (const float*)d_in[22];
    const float* cp_b1  = (const float*)d_in[23];
    const float* cp_w2  = (const float*)d_in[24];
    const float* cp_b2  = (const float*)d_in[25];

    int N = in_sizes[0] / 4;
    int E = in_sizes[2] / 5;
    int B = in_sizes[4] / HS;
    int BE = B * NEG;
    const int* src = ei;
    const int* dst = ei + E;

    float* out  = (float*)d_out;
    float* Tout = out;
    float* Dout = out + BE;
    float* Hout = out + 2 * BE;

    k_init<<<N + E, HD>>>(x, ea, node_w, node_b, edgep_w, edgep_b, N);

    int nb_n = (N + 7) / 8, nb_e = (E + 7) / 8;
    for (int l = 0; l < NLAYER; l++) {
        k_attn   <<<nb_n + nb_e, HD>>>(gat_lin + l * HD * HD, att_src + l * HEADS * CDIM,
                                       att_dst + l * HEADS * CDIM, gat_le + l * HD * HD,
                                       att_ed + l * HEADS * CDIM, N, E, nb_n);
        k_edgeagg<<<E + N, HD>>>(src, dst, N, E);
        k_ln     <<<N, HD>>>(gat_b + l * HD, ln_s + l * HD, ln_b + l * HD);
    }

    k_mlp<<<nb_n + nb_e, 64>>>(on_w1, on_b1, on_w2, on_b2,
                               cp_w1, cp_b1, cp_w2, cp_b2, N, E, nb_n);
    k_dna<<<1, 1024>>>(x, N, B);
    int tot = N + E + B * HS;
    k_basm<<<(tot + 255) / 256, 256>>>(src, dst, batch, GL, GR, N, E, B);
    k_lu  <<<64, 256>>>(Hout, BE, B);
    k_solve<<<BE * 4, 32>>>(GL, GR, Tout, Dout, BE);
}

// round 11
// speedup vs baseline: 1.2132x; 1.0023x over previous
#include <cuda_runtime.h>
#include <cuda_device_runtime_api.h>
#include <math.h>

#define HD     128
#define HEADS  4
#define CDIM   32
#define NLAYER 4
#define NEG    100
#define HS     128

#define N_MAX  2048
#define E_MAX  4096
#define B_MAX  32
#define BE_MAX (B_MAX * NEG)

#if defined(__CUDA_ARCH__) && (__CUDA_ARCH__ >= 900)
#define GDS() cudaGridDependencySynchronize()
#else
#define GDS()
#endif

// ---------------- scratch (device globals; no allocation allowed) ----------
__device__ float g_h   [N_MAX * HD];
__device__ float g_e   [E_MAX * HD];
__device__ float g_xl  [N_MAX * HD];
__device__ float g_ssrc[N_MAX * HEADS];
__device__ float g_sdst[N_MAX * HEADS];
__device__ float g_ae  [E_MAX * HEADS];
__device__ float g_aesum[HEADS];
__device__ float g_den  [N_MAX * HEADS];
__device__ float g_agg  [N_MAX * HD];
__device__ float g_onsite[N_MAX];
__device__ float g_coup  [E_MAX];
__device__ int   g_dna  [N_MAX];
__device__ int   g_loc  [N_MAX];
// NEGF scratch
__device__ float g_hbd[B_MAX * HS];
__device__ float g_hb1[B_MAX * HS];
__device__ float g_hb2[B_MAX * HS];
__device__ float g_dvb[B_MAX * HS];
__device__ float2 g_lu[BE_MAX * 5 * HS];
__device__ float g_Tacc[BE_MAX];
__device__ float g_Dacc[BE_MAX];
__device__ int   g_cnt [BE_MAX];

// complex mul / fms helpers
#define CMUL(o, a, b) do { \
    (o).x = (a).x * (b).x - (a).y * (b).y; \
    (o).y = (a).x * (b).y + (a).y * (b).x; \
} while (0)
#define CFMS(m, c, r) do { \
    (m).x = fmaf(-(c).x, (r).x, fmaf((c).y, (r).y, (m).x)); \
    (m).y = fmaf(-(c).x, (r).y, fmaf(-(c).y, (r).x, (m).y)); \
} while (0)

// ---------------- GNN kernels ----------------------------------------------
// merged node+edge input projections (one launch)
__global__ void k_init(const float* __restrict__ x, const float* __restrict__ ea,
                       const float* __restrict__ nw, const float* __restrict__ nb,
                       const float* __restrict__ ew, const float* __restrict__ eb,
                       int N) {
    GDS();
    int r = blockIdx.x, t = threadIdx.x;
    if (r < N) {
        float acc = nb[t];
#pragma unroll
        for (int k = 0; k < 4; k++) acc = fmaf(x[r * 4 + k], nw[k * HD + t], acc);
        g_h[r * HD + t] = acc;
        g_agg[r * HD + t] = 0.f;
        if (t < HEADS) g_den[r * HEADS + t] = 0.f;
        if (r == 0 && t < HEADS) g_aesum[t] = 0.f;
    } else {
        int e = r - N;
        float acc = eb[t];
#pragma unroll
        for (int k = 0; k < 5; k++) acc = fmaf(ea[e * 5 + k], ew[k * HD + t], acc);
        g_e[e * HD + t] = acc;
    }
}

// fused xl (nodes) + edge-attention projection: 4 rows per block (round-8 shape)
__global__ void k_attn(const float* __restrict__ Wn, const float* __restrict__ asrc,
                       const float* __restrict__ adst, const float* __restrict__ We,
                       const float* __restrict__ aedge, int N, int E, int nb_n) {
    __shared__ float rows[4][HD];
    __shared__ float outs[4][HD];
    GDS();
    int t = threadIdx.x;
    bool isnode = (blockIdx.x < nb_n);
    int r0 = (isnode ? blockIdx.x : blockIdx.x - nb_n) * 4;
    int cnt = (isnode ? N : E) - r0; if (cnt > 4) cnt = 4;
    const float* base = isnode ? g_h : g_e;
    const float* W = isnode ? Wn : We;
#pragma unroll
    for (int rr = 0; rr < 4; rr++)
        rows[rr][t] = (rr < cnt) ? base[(size_t)(r0 + rr) * HD + t] : 0.f;
    __syncthreads();
    float a0 = 0.f, a1 = 0.f, a2 = 0.f, a3 = 0.f;
#pragma unroll 4
    for (int k = 0; k < HD; k++) {
        float wv = W[k * HD + t];
        a0 = fmaf(rows[0][k], wv, a0);
        a1 = fmaf(rows[1][k], wv, a1);
        a2 = fmaf(rows[2][k], wv, a2);
        a3 = fmaf(rows[3][k], wv, a3);
    }
    outs[0][t] = a0; outs[1][t] = a1; outs[2][t] = a2; outs[3][t] = a3;
    if (isnode) {
        if (0 < cnt) g_xl[(size_t)(r0 + 0) * HD + t] = a0;
        if (1 < cnt) g_xl[(size_t)(r0 + 1) * HD + t] = a1;
        if (2 < cnt) g_xl[(size_t)(r0 + 2) * HD + t] = a2;
        if (3 < cnt) g_xl[(size_t)(r0 + 3) * HD + t] = a3;
    }
    __syncthreads();
    int w = t >> 5, lane = t & 31;
    if (w < cnt) {
        if (isnode) {
#pragma unroll
            for (int h = 0; h < HEADS; h++) {
                float xv = outs[w][h * 32 + lane];
                float vs = xv * asrc[h * 32 + lane];
                float vd = xv * adst[h * 32 + lane];
#pragma unroll
                for (int o = 16; o > 0; o >>= 1) {
                    vs += __shfl_down_sync(0xffffffffu, vs, o);
                    vd += __shfl_down_sync(0xffffffffu, vd, o);
                }
                if (lane == 0) {
                    g_ssrc[(r0 + w) * HEADS + h] = vs;
                    g_sdst[(r0 + w) * HEADS + h] = vd;
                }
            }
        } else {
#pragma unroll
            for (int h = 0; h < HEADS; h++) {
                float v = outs[w][h * 32 + lane] * aedge[h * 32 + lane];
#pragma unroll
                for (int o = 16; o > 0; o >>= 1)
                    v += __shfl_down_sync(0xffffffffu, v, o);
                if (lane == 0) {
                    g_ae[(r0 + w) * HEADS + h] = v;
                    atomicAdd(&g_aesum[h], v);
                }
            }
        }
    }
}

// fused attention-weight + aggregation (softmax shift cancels exactly)
__global__ void k_edgeagg(const int* __restrict__ src, const int* __restrict__ dst,
                          int N, int E) {
    GDS();
    int f = blockIdx.x, t = threadIdx.x;
    int hh = t >> 5, lane = t & 31;
    int s, d; float ae;
    if (f < E) { s = src[f]; d = dst[f]; ae = g_ae[f * HEADS + hh]; }
    else       { s = f - E; d = s;       ae = g_aesum[hh] / (float)E; }
    float a = g_ssrc[s * HEADS + hh] + g_sdst[d * HEADS + hh] + ae;
    a = a > 0.f ? a : 0.2f * a;
    float ex = expf(a);
    atomicAdd(&g_agg[d * HD + t], g_xl[(size_t)s * HD + t] * ex);
    if (lane == 0) atomicAdd(&g_den[d * HEADS + hh], ex);
}

// layernorm(relu(agg/den + bias) + h); zero accumulators for the next layer
__global__ void k_ln(const float* __restrict__ bias, const float* __restrict__ s,
                     const float* __restrict__ bb) {
    __shared__ float redh[4], redv[4];
    GDS();
    int n = blockIdx.x, t = threadIdx.x;
    int w = t >> 5, lane = t & 31;
    float den = g_den[n * HEADS + w];
    float v = g_agg[n * HD + t] / den + bias[t];
    g_agg[n * HD + t] = 0.f;
    if (t < HEADS) g_den[n * HEADS + t] = 0.f;
    v = v > 0.f ? v : 0.f;
    v += g_h[n * HD + t];
    float s1 = v;
#pragma unroll
    for (int o = 16; o > 0; o >>= 1) s1 += __shfl_down_sync(0xffffffffu, s1, o);
    if (lane == 0) redh[w] = s1;
    __syncthreads();
    float mu = (redh[0] + redh[1] + redh[2] + redh[3]) * (1.f / HD);
    float dd = v - mu;
    float s2 = dd * dd;
#pragma unroll
    for (int o = 16; o > 0; o >>= 1) s2 += __shfl_down_sync(0xffffffffu, s2, o);
    if (lane == 0) redv[w] = s2;
    __syncthreads();
    float var = (redv[0] + redv[1] + redv[2] + redv[3]) * (1.f / HD);
    g_h[n * HD + t] = dd * rsqrtf(var + 1e-5f) * s[t] + bb[t];
    if (n == 0 && t < HEADS) g_aesum[t] = 0.f;
}

// onsite (nodes) + coupling (edges) MLPs: one row per block (round-8 shape)
__global__ void k_mlp(const float* __restrict__ w1, const float* __restrict__ b1,
                      const float* __restrict__ w2, const float* __restrict__ b2,
                      const float* __restrict__ cw1, const float* __restrict__ cb1,
                      const float* __restrict__ cw2, const float* __restrict__ cb2,
                      int N) {
    __shared__ float in[HD];
    __shared__ float red[64];
    GDS();
    int blk = blockIdx.x, t = threadIdx.x;
    const float *row, *W1, *B1, *W2, *B2;
    if (blk < N) { row = &g_h[(size_t)blk * HD];       W1 = w1;  B1 = b1;  W2 = w2;  B2 = b2;  }
    else         { row = &g_e[(size_t)(blk - N) * HD]; W1 = cw1; B1 = cb1; W2 = cw2; B2 = cb2; }
    in[t] = row[t]; in[t + 64] = row[t + 64];
    __syncthreads();
    float acc = B1[t];
#pragma unroll 8
    for (int k = 0; k < HD; k++) acc = fmaf(in[k], W1[k * 64 + t], acc);
    acc = acc > 0.f ? acc : 0.f;
    red[t] = acc * W2[t];
    __syncthreads();
#pragma unroll
    for (int o = 32; o > 0; o >>= 1) { if (t < o) red[t] += red[t + o]; __syncthreads(); }
    if (t == 0) {
        float o = red[0] + B2[0];
        if (blk < N) g_onsite[blk] = o; else g_coup[blk - N] = o;
    }
}

// dna mask + local index: warp-per-graph ballot scan (graphs contiguous,
// uniform size N/B -- same construction guarantee as the band structure)
__global__ void k_dna(const float* __restrict__ x, int N, int B) {
    GDS();
    int t = threadIdx.x;
    for (int i = t; i < B * HS; i += blockDim.x) {
        g_hbd[i] = 0.f; g_hb1[i] = 0.f; g_hb2[i] = 0.f;
    }
    int warp = t >> 5, lane = t & 31;
    int npg = N / B;
    if (warp < B) {
        int base = warp * npg;
        int off = 0;
        for (int c = 0; c < npg; c += 32) {
            int li = c + lane;
            int mi = 0;
            if (li < npg) {
                int n = base + li;
                float a = x[n * 4], b = x[n * 4 + 1], cc = x[n * 4 + 2], d = x[n * 4 + 3];
                mi = (a != 0.f || b != 0.f || cc != 0.f || d != 0.f) ? 1 : 0;
                g_dna[n] = mi;
            }
            unsigned bits = __ballot_sync(0xffffffffu, mi);
            if (li < npg) g_loc[base + li] = off + __popc(bits & ((1u << lane) - 1u));
            off += __popc(bits);
        }
    }
}

// assemble bands: onsite->diag, coup->band1/band2, dvb from GL/GR
__global__ void k_basm(const int* __restrict__ src, const int* __restrict__ dst,
                       const int* __restrict__ batch,
                       const float* __restrict__ GL, const float* __restrict__ GR,
                       int N, int E, int B) {
    GDS();
    int idx = blockIdx.x * blockDim.x + threadIdx.x;
    if (idx < N) {
        if (g_dna[idx])
            atomicAdd(&g_hbd[batch[idx] * HS + g_loc[idx]], g_onsite[idx]);
    } else if (idx < N + E) {
        int e = idx - N;
        int s = src[e], d = dst[e];
        if (g_dna[s] && g_dna[d]) {
            int b = batch[s], u = g_loc[s], v = g_loc[d];
            int lo = u < v ? u : v;
            int bd = u < v ? v - u : u - v;
            float cv = g_coup[e];
            if (bd == 1)      atomicAdd(&g_hb1[b * HS + lo], cv);
            else if (bd == 2) atomicAdd(&g_hb2[b * HS + lo], cv);
        }
    } else if (idx < N + E + B * HS) {
        int i = idx - N - E;
        g_dvb[i] = 0.5f * (GL[i] + GR[i]) + 1e-12f;
    }
}

// banded LU (one thread per (b,e)) + dense H output write (grid-stride)
__global__ void k_lu(float* __restrict__ Hout, int BE, int B) {
    GDS();
    int gtid = blockIdx.x * blockDim.x + threadIdx.x;
    int nthr = gridDim.x * blockDim.x;

    // dense H (output) from bands
    int tot = B * HS * HS;
    for (int idx = gtid; idx < tot; idx += nthr) {
        int bb = idx / (HS * HS);
        int r = (idx % (HS * HS)) / HS, c = idx % HS;
        int lo = r < c ? r : c;
        int bd = r < c ? c - r : r - c;
        float v;
        if (bd == 0)      v = g_hbd[bb * HS + r] + 1e-6f;
        else if (bd == 1) v = g_hb1[bb * HS + lo];
        else if (bd == 2) v = g_hb2[bb * HS + lo];
        else              v = 0.f;
        Hout[idx] = v;
    }

    for (int be = gtid; be < BE; be += nthr) {
        int b = be / NEG, e = be % NEG;
        float Eg = (float)(-3.0 + 6.0 * (double)e / 99.0);
        const float* hd = g_hbd + b * HS;
        const float* h1 = g_hb1 + b * HS;
        const float* h2 = g_hb2 + b * HS;
        const float* dv = g_dvb + b * HS;
        float2* out = g_lu + (size_t)be * 5 * HS;
        g_Tacc[be] = 0.f; g_Dacc[be] = 0.f; g_cnt[be] = 0;

        float2 e1 = {0.f, 0.f}, e2 = {0.f, 0.f};
        float2 f1 = {0.f, 0.f}, f2 = {0.f, 0.f};
        float2 di1 = {0.f, 0.f}, di2 = {0.f, 0.f};
        for (int i = 0; i < HS; i++) {
            float2 Mi = make_float2(Eg - (hd[i] + 1e-6f), dv[i]);
            float m1 = (i >= 1) ? -h1[i - 1] : 0.f;
            float m2 = (i >= 2) ? -h2[i - 2] : 0.f;
            float2 bi = make_float2(m2 * di2.x, m2 * di2.y);
            float2 tt = make_float2(m1, 0.f);
            CFMS(tt, bi, e2);
            float2 ai; CMUL(ai, tt, di1);
            float2 d = Mi;
            CFMS(d, bi, f2);
            CFMS(d, ai, e1);
            float2 ei = make_float2(0.f, 0.f);
            if (i < HS - 1) { ei = make_float2(-h1[i], 0.f); CFMS(ei, ai, f1); }
            float2 fi = make_float2((i < HS - 2) ? -h2[i] : 0.f, 0.f);
            float inv = 1.f / fmaf(d.x, d.x, d.y * d.y);
            float2 dinv = make_float2(d.x * inv, -d.y * inv);
            out[0 * HS + i] = ai;
            out[1 * HS + i] = bi;
            out[2 * HS + i] = ei;
            out[3 * HS + i] = fi;
            out[4 * HS + i] = dinv;
            e2 = e1; e1 = ei; f2 = f1; f1 = fi; di2 = di1; di1 = dinv;
        }
    }
}

// column solves: one warp-CTA per (b,e, quarter); lane = column j.
// Last CTA per (b,e) writes the final log10 outputs.
__global__ void __launch_bounds__(32) k_solve(
    const float* __restrict__ GL, const float* __restrict__ GR,
    float* __restrict__ Tout, float* __restrict__ Dout, int BE) {
    __shared__ float2 ys[HS * 32];
    __shared__ float2 sa[HS], sb[HS], se[HS], sf[HS], sdi[HS];
    __shared__ float  sgl[HS], sgr[HS];
    GDS();
    int blk = blockIdx.x;
    int be = blk >> 2, q = blk & 3;
    int b = be / NEG;
    int lane = threadIdx.x;
    const float2* lu = g_lu + (size_t)be * 5 * HS;
#pragma unroll
    for (int k = 0; k < 4; k++) {
        int i = lane + k * 32;
        sa[i]  = lu[0 * HS + i];
        sb[i]  = lu[1 * HS + i];
        se[i]  = lu[2 * HS + i];
        sf[i]  = lu[3 * HS + i];
        sdi[i] = lu[4 * HS + i];
        sgl[i] = GL[b * HS + i];
        sgr[i] = GR[b * HS + i];
    }
    __syncwarp();

    int j = q * 32 + lane;
    int i0 = q * 32;
    float2 y1 = {0.f, 0.f}, y2 = {0.f, 0.f};
    for (int i = i0; i < HS; i++) {
        float2 y = make_float2((i == j) ? 1.f : 0.f, 0.f);
        CFMS(y, sa[i], y1);
        CFMS(y, sb[i], y2);
        ys[i * 32 + lane] = y;
        y2 = y1; y1 = y;
    }
    float2 x1 = {0.f, 0.f}, x2 = {0.f, 0.f};
    float tp = 0.f, dj = 0.f;
    for (int i = HS - 1; i >= 0; i--) {
        float2 t = (i >= i0) ? ys[i * 32 + lane] : make_float2(0.f, 0.f);
        CFMS(t, se[i], x1);
        CFMS(t, sf[i], x2);
        float2 xx; CMUL(xx, t, sdi[i]);
        tp = fmaf(sgl[i], fmaf(xx.x, xx.x, xx.y * xx.y), tp);
        if (i == j) dj = xx.y;
        x2 = x1; x1 = xx;
    }
    tp *= sgr[j];
#pragma unroll
    for (int o = 16; o > 0; o >>= 1) {
        tp += __shfl_down_sync(0xffffffffu, tp, o);
        dj += __shfl_down_sync(0xffffffffu, dj, o);
    }
    if (lane == 0) {
        atomicAdd(&g_Tacc[be], tp);
        atomicAdd(&g_Dacc[be], dj);
        __threadfence();
        int old = atomicAdd(&g_cnt[be], 1);
        if (old == 3) {
            __threadfence();
            Tout[be] = log10f(fmaxf(g_Tacc[be], 1e-16f));
            Dout[be] = log10f(fmaxf(-g_Dacc[be] / 3.14159265358979323846f, 1e-16f));
        }
    }
}

// ---------------- PDL launch helper -----------------------------------------
template <typename F, typename... Args>
static void plaunch(F f, int grid, int block, Args... args) {
    cudaLaunchConfig_t cfg = {};
    cfg.gridDim = dim3(grid, 1, 1);
    cfg.blockDim = dim3(block, 1, 1);
    cfg.dynamicSmemBytes = 0;
    cfg.stream = 0;
    cudaLaunchAttribute at[1];
    at[0].id = cudaLaunchAttributeProgrammaticStreamSerialization;
    at[0].val.programmaticStreamSerializationAllowed = 1;
    cfg.attrs = at;
    cfg.numAttrs = 1;
    cudaLaunchKernelEx(&cfg, f, args...);
}

// ---------------- launch ----------------------------------------------------
extern "C" void kernel_launch(void* const* d_in, const int* in_sizes, int n_in,
                              void* d_out, int out_size) {
    const float* x      = (const float*)d_in[0];
    const int*   ei     = (const int*)  d_in[1];
    const float* ea     = (const float*)d_in[2];
    const int*   batch  = (const int*)  d_in[3];
    const float* GL     = (const float*)d_in[4];
    const float* GR     = (const float*)d_in[5];
    const float* node_w = (const float*)d_in[6];
    const float* node_b = (const float*)d_in[7];
    const float* edgep_w= (const float*)d_in[8];
    const float* edgep_b= (const float*)d_in[9];
    const float* gat_lin= (const float*)d_in[10];
    const float* att_src= (const float*)d_in[11];
    const float* att_dst= (const float*)d_in[12];
    const float* gat_le = (const float*)d_in[13];
    const float* att_ed = (const float*)d_in[14];
    const float* gat_b  = (const float*)d_in[15];
    const float* ln_s   = (const float*)d_in[16];
    const float* ln_b   = (const float*)d_in[17];
    const float* on_w1  = (const float*)d_in[18];
    const float* on_b1  = (const float*)d_in[19];
    const float* on_w2  = (const float*)d_in[20];
    const float* on_b2  = (const float*)d_in[21];
    const float* cp_w1  = (const float*)d_in[22];
    const float* cp_b1  = (const float*)d_in[23];
    const float* cp_w2  = (const float*)d_in[24];
    const float* cp_b2  = (const float*)d_in[25];

    int N = in_sizes[0] / 4;
    int E = in_sizes[2] / 5;
    int B = in_sizes[4] / HS;
    int BE = B * NEG;
    const int* src = ei;
    const int* dst = ei + E;

    float* out  = (float*)d_out;
    float* Tout = out;
    float* Dout = out + BE;
    float* Hout = out + 2 * BE;

    plaunch(k_init, N + E, HD, x, ea, node_w, node_b, edgep_w, edgep_b, N);

    int nb_n = (N + 3) / 4, nb_e = (E + 3) / 4;
    for (int l = 0; l < NLAYER; l++) {
        plaunch(k_attn, nb_n + nb_e, HD,
                gat_lin + l * HD * HD, att_src + l * HEADS * CDIM,
                att_dst + l * HEADS * CDIM, gat_le + l * HD * HD,
                att_ed + l * HEADS * CDIM, N, E, nb_n);
        plaunch(k_edgeagg, E + N, HD, src, dst, N, E);
        plaunch(k_ln, N, HD, gat_b + l * HD, ln_s + l * HD, ln_b + l * HD);
    }

    plaunch(k_mlp, N + E, 64, on_w1, on_b1, on_w2, on_b2,
            cp_w1, cp_b1, cp_w2, cp_b2, N);
    plaunch(k_dna, 1, 1024, x, N, B);
    int tot = N + E + B * HS;
    plaunch(k_basm, (tot + 255) / 256, 256, src, dst, batch, GL, GR, N, E, B);
    plaunch(k_lu, 128, 256, Hout, BE, B);
    plaunch(k_solve, BE * 4, 32, GL, GR, Tout, Dout, BE);
}

// round 13
// speedup vs baseline: 1.5090x; 1.2439x over previous
#include <cuda_runtime.h>
#include <math.h>

#define HD     128
#define HEADS  4
#define CDIM   32
#define NLAYER 4
#define NEG    100
#define HS     128

#define N_MAX  2048
#define E_MAX  4096
#define B_MAX  32
#define BE_MAX (B_MAX * NEG)

// ---------------- scratch (device globals; no allocation allowed) ----------
__device__ float g_h   [N_MAX * HD];
__device__ float g_e   [E_MAX * HD];
__device__ float g_xl  [N_MAX * HD];
__device__ float g_ssrc[N_MAX * HEADS];
__device__ float g_sdst[N_MAX * HEADS];
__device__ float g_ae  [E_MAX * HEADS];
__device__ float g_aesum[HEADS];
__device__ float g_den  [N_MAX * HEADS];
__device__ float g_agg  [N_MAX * HD];
__device__ float g_onsite[N_MAX];
__device__ float g_coup  [E_MAX];
__device__ int   g_dna  [N_MAX];
__device__ int   g_loc  [N_MAX];
// NEGF scratch
__device__ float g_hbd[B_MAX * HS];
__device__ float g_hb1[B_MAX * HS];
__device__ float g_hb2[B_MAX * HS];
__device__ float g_dvb[B_MAX * HS];
__device__ float2 g_lu[BE_MAX * 5 * HS];
__device__ float g_Tacc[BE_MAX];
__device__ float g_Dacc[BE_MAX];
__device__ int   g_cnt [BE_MAX];

// complex mul / fms helpers
#define CMUL(o, a, b) do { \
    (o).x = (a).x * (b).x - (a).y * (b).y; \
    (o).y = (a).x * (b).y + (a).y * (b).x; \
} while (0)
#define CFMS(m, c, r) do { \
    (m).x = fmaf(-(c).x, (r).x, fmaf((c).y, (r).y, (m).x)); \
    (m).y = fmaf(-(c).x, (r).y, fmaf(-(c).y, (r).x, (m).y)); \
} while (0)

// ---------------- GNN kernels ----------------------------------------------
__global__ void k_init_h(const float* __restrict__ x, const float* __restrict__ w,
                         const float* __restrict__ b) {
    int n = blockIdx.x, t = threadIdx.x;
    float acc = b[t];
#pragma unroll
    for (int k = 0; k < 4; k++) acc = fmaf(x[n * 4 + k], w[k * HD + t], acc);
    g_h[n * HD + t] = acc;
    g_agg[n * HD + t] = 0.f;
    if (t < HEADS) g_den[n * HEADS + t] = 0.f;
    if (n == 0 && t < HEADS) g_aesum[t] = 0.f;
}

__global__ void k_init_e(const float* __restrict__ ea, const float* __restrict__ w,
                         const float* __restrict__ b) {
    int n = blockIdx.x, t = threadIdx.x;
    float acc = b[t];
#pragma unroll
    for (int k = 0; k < 5; k++) acc = fmaf(ea[n * 5 + k], w[k * HD + t], acc);
    g_e[n * HD + t] = acc;
}

// fused xl (nodes) + edge-attention projection: 4 rows per block
__global__ void k_attn(const float* __restrict__ Wn, const float* __restrict__ asrc,
                       const float* __restrict__ adst, const float* __restrict__ We,
                       const float* __restrict__ aedge, int N, int E, int nb_n) {
    __shared__ float rows[4][HD];
    __shared__ float outs[4][HD];
    int t = threadIdx.x;
    bool isnode = (blockIdx.x < nb_n);
    int r0 = (isnode ? blockIdx.x : blockIdx.x - nb_n) * 4;
    int cnt = (isnode ? N : E) - r0; if (cnt > 4) cnt = 4;
    const float* base = isnode ? g_h : g_e;
    const float* W = isnode ? Wn : We;
#pragma unroll
    for (int rr = 0; rr < 4; rr++)
        rows[rr][t] = (rr < cnt) ? base[(size_t)(r0 + rr) * HD + t] : 0.f;
    __syncthreads();
    float a0 = 0.f, a1 = 0.f, a2 = 0.f, a3 = 0.f;
#pragma unroll 4
    for (int k = 0; k < HD; k++) {
        float wv = W[k * HD + t];
        a0 = fmaf(rows[0][k], wv, a0);
        a1 = fmaf(rows[1][k], wv, a1);
        a2 = fmaf(rows[2][k], wv, a2);
        a3 = fmaf(rows[3][k], wv, a3);
    }
    outs[0][t] = a0; outs[1][t] = a1; outs[2][t] = a2; outs[3][t] = a3;
    if (isnode) {
        if (0 < cnt) g_xl[(size_t)(r0 + 0) * HD + t] = a0;
        if (1 < cnt) g_xl[(size_t)(r0 + 1) * HD + t] = a1;
        if (2 < cnt) g_xl[(size_t)(r0 + 2) * HD + t] = a2;
        if (3 < cnt) g_xl[(size_t)(r0 + 3) * HD + t] = a3;
    }
    __syncthreads();
    int w = t >> 5, lane = t & 31;
    if (w < cnt) {
        if (isnode) {
#pragma unroll
            for (int h = 0; h < HEADS; h++) {
                float xv = outs[w][h * 32 + lane];
                float vs = xv * asrc[h * 32 + lane];
                float vd = xv * adst[h * 32 + lane];
#pragma unroll
                for (int o = 16; o > 0; o >>= 1) {
                    vs += __shfl_down_sync(0xffffffffu, vs, o);
                    vd += __shfl_down_sync(0xffffffffu, vd, o);
                }
                if (lane == 0) {
                    g_ssrc[(r0 + w) * HEADS + h] = vs;
                    g_sdst[(r0 + w) * HEADS + h] = vd;
                }
            }
        } else {
#pragma unroll
            for (int h = 0; h < HEADS; h++) {
                float v = outs[w][h * 32 + lane] * aedge[h * 32 + lane];
#pragma unroll
                for (int o = 16; o > 0; o >>= 1)
                    v += __shfl_down_sync(0xffffffffu, v, o);
                if (lane == 0) {
                    g_ae[(r0 + w) * HEADS + h] = v;
                    atomicAdd(&g_aesum[h], v);
                }
            }
        }
    }
}

// fused attention-weight + aggregation (softmax shift cancels exactly):
// U[d] += xl[s]*exp(alpha), den[d] += exp(alpha); k_ln divides.
__global__ void k_edgeagg(const int* __restrict__ src, const int* __restrict__ dst,
                          int N, int E) {
    int f = blockIdx.x, t = threadIdx.x;
    int hh = t >> 5, lane = t & 31;
    int s, d; float ae;
    if (f < E) { s = src[f]; d = dst[f]; ae = g_ae[f * HEADS + hh]; }
    else       { s = f - E; d = s;       ae = g_aesum[hh] / (float)E; }
    float a = g_ssrc[s * HEADS + hh] + g_sdst[d * HEADS + hh] + ae;
    a = a > 0.f ? a : 0.2f * a;
    float ex = expf(a);
    atomicAdd(&g_agg[d * HD + t], g_xl[(size_t)s * HD + t] * ex);
    if (lane == 0) atomicAdd(&g_den[d * HEADS + hh], ex);
}

// layernorm(relu(agg/den + bias) + h); zero accumulators for the next layer
__global__ void k_ln(const float* __restrict__ bias, const float* __restrict__ s,
                     const float* __restrict__ bb) {
    __shared__ float red[HD];
    int n = blockIdx.x, t = threadIdx.x;
    float den = g_den[n * HEADS + (t >> 5)];
    float v = g_agg[n * HD + t] / den + bias[t];
    g_agg[n * HD + t] = 0.f;
    if (t < HEADS) g_den[n * HEADS + t] = 0.f;
    v = v > 0.f ? v : 0.f;
    v += g_h[n * HD + t];
    red[t] = v; __syncthreads();
#pragma unroll
    for (int o = 64; o > 0; o >>= 1) { if (t < o) red[t] += red[t + o]; __syncthreads(); }
    float mu = red[0] / (float)HD;
    __syncthreads();
    float dd = v - mu;
    red[t] = dd * dd; __syncthreads();
#pragma unroll
    for (int o = 64; o > 0; o >>= 1) { if (t < o) red[t] += red[t + o]; __syncthreads(); }
    float var = red[0] / (float)HD;
    g_h[n * HD + t] = dd * rsqrtf(var + 1e-5f) * s[t] + bb[t];
    if (n == 0 && t < HEADS) g_aesum[t] = 0.f;
}

// onsite (nodes) + coupling (edges) MLPs: 128 -> 64 (relu) -> 1
__global__ void k_mlp(const float* __restrict__ w1, const float* __restrict__ b1,
                      const float* __restrict__ w2, const float* __restrict__ b2,
                      const float* __restrict__ cw1, const float* __restrict__ cb1,
                      const float* __restrict__ cw2, const float* __restrict__ cb2,
                      int N) {
    __shared__ float in[HD];
    __shared__ float red[64];
    int blk = blockIdx.x, t = threadIdx.x;
    const float *row, *W1, *B1, *W2, *B2;
    if (blk < N) { row = &g_h[(size_t)blk * HD];       W1 = w1;  B1 = b1;  W2 = w2;  B2 = b2;  }
    else         { row = &g_e[(size_t)(blk - N) * HD]; W1 = cw1; B1 = cb1; W2 = cw2; B2 = cb2; }
    in[t] = row[t]; in[t + 64] = row[t + 64];
    __syncthreads();
    float acc = B1[t];
#pragma unroll 8
    for (int k = 0; k < HD; k++) acc = fmaf(in[k], W1[k * 64 + t], acc);
    acc = acc > 0.f ? acc : 0.f;
    red[t] = acc * W2[t];
    __syncthreads();
#pragma unroll
    for (int o = 32; o > 0; o >>= 1) { if (t < o) red[t] += red[t + o]; __syncthreads(); }
    if (t == 0) {
        float o = red[0] + B2[0];
        if (blk < N) g_onsite[blk] = o; else g_coup[blk - N] = o;
    }
}

// dna mask + local index: warp-per-graph ballot scan (graphs contiguous,
// uniform size N/B -- same construction guarantee as the band structure);
// also zeroes band arrays for k_basm.
__global__ void k_dna(const float* __restrict__ x, int N, int B) {
    int t = threadIdx.x;
    for (int i = t; i < B * HS; i += blockDim.x) {
        g_hbd[i] = 0.f; g_hb1[i] = 0.f; g_hb2[i] = 0.f;
    }
    int warp = t >> 5, lane = t & 31;
    int npg = N / B;
    if (warp < B) {
        int base = warp * npg;
        int off = 0;
        for (int c = 0; c < npg; c += 32) {
            int li = c + lane;
            int mi = 0;
            if (li < npg) {
                int n = base + li;
                float a = x[n * 4], b = x[n * 4 + 1], cc = x[n * 4 + 2], d = x[n * 4 + 3];
                mi = (a != 0.f || b != 0.f || cc != 0.f || d != 0.f) ? 1 : 0;
                g_dna[n] = mi;
            }
            unsigned bits = __ballot_sync(0xffffffffu, mi);
            if (li < npg) g_loc[base + li] = off + __popc(bits & ((1u << lane) - 1u));
            off += __popc(bits);
        }
    }
}

// assemble bands: onsite->diag, coup->band1/band2, dvb from GL/GR
__global__ void k_basm(const int* __restrict__ src, const int* __restrict__ dst,
                       const int* __restrict__ batch,
                       const float* __restrict__ GL, const float* __restrict__ GR,
                       int N, int E, int B) {
    int idx = blockIdx.x * blockDim.x + threadIdx.x;
    if (idx < N) {
        if (g_dna[idx])
            atomicAdd(&g_hbd[batch[idx] * HS + g_loc[idx]], g_onsite[idx]);
    } else if (idx < N + E) {
        int e = idx - N;
        int s = src[e], d = dst[e];
        if (g_dna[s] && g_dna[d]) {
            int b = batch[s], u = g_loc[s], v = g_loc[d];
            int lo = u < v ? u : v;
            int bd = u < v ? v - u : u - v;
            float cv = g_coup[e];
            if (bd == 1)      atomicAdd(&g_hb1[b * HS + lo], cv);
            else if (bd == 2) atomicAdd(&g_hb2[b * HS + lo], cv);
        }
    } else if (idx < N + E + B * HS) {
        int i = idx - N - E;
        g_dvb[i] = 0.5f * (GL[i] + GR[i]) + 1e-12f;
    }
}

// write dense H (output) from bands
__global__ void k_hwrite(float* __restrict__ H, int B) {
    int idx = blockIdx.x * blockDim.x + threadIdx.x;
    if (idx >= B * HS * HS) return;
    int b = idx / (HS * HS);
    int r = (idx % (HS * HS)) / HS, c = idx % HS;
    float v;
    int lo = r < c ? r : c;
    int bd = r < c ? c - r : r - c;
    if (bd == 0)      v = g_hbd[b * HS + r] + 1e-6f;
    else if (bd == 1) v = g_hb1[b * HS + lo];
    else if (bd == 2) v = g_hb2[b * HS + lo];
    else              v = 0.f;
    H[idx] = v;
}

// ---------------- NEGF: banded (pentadiagonal) solver ----------------------
// banded LU: one thread per (b,e); writes a,b,e,f,dinv bands to g_lu
__global__ void k_lu(int BE) {
    int be = blockIdx.x * blockDim.x + threadIdx.x;
    if (be >= BE) return;
    int b = be / NEG, e = be % NEG;
    float Eg = (float)(-3.0 + 6.0 * (double)e / 99.0);
    const float* hd = g_hbd + b * HS;
    const float* h1 = g_hb1 + b * HS;
    const float* h2 = g_hb2 + b * HS;
    const float* dv = g_dvb + b * HS;
    float2* out = g_lu + (size_t)be * 5 * HS;
    g_Tacc[be] = 0.f; g_Dacc[be] = 0.f; g_cnt[be] = 0;

    float2 e1 = {0.f, 0.f}, e2 = {0.f, 0.f};
    float2 f1 = {0.f, 0.f}, f2 = {0.f, 0.f};
    float2 di1 = {0.f, 0.f}, di2 = {0.f, 0.f};
    for (int i = 0; i < HS; i++) {
        float2 Mi = make_float2(Eg - (hd[i] + 1e-6f), dv[i]);
        float m1 = (i >= 1) ? -h1[i - 1] : 0.f;
        float m2 = (i >= 2) ? -h2[i - 2] : 0.f;
        float2 bi = make_float2(m2 * di2.x, m2 * di2.y);
        float2 tt = make_float2(m1, 0.f);
        CFMS(tt, bi, e2);                          // m1 - bi*e2
        float2 ai; CMUL(ai, tt, di1);              // / d_{i-1}
        float2 d = Mi;
        CFMS(d, bi, f2);
        CFMS(d, ai, e1);
        float2 ei = make_float2(0.f, 0.f);
        if (i < HS - 1) { ei = make_float2(-h1[i], 0.f); CFMS(ei, ai, f1); }
        float2 fi = make_float2((i < HS - 2) ? -h2[i] : 0.f, 0.f);
        float inv = 1.f / fmaf(d.x, d.x, d.y * d.y);
        float2 dinv = make_float2(d.x * inv, -d.y * inv);
        out[0 * HS + i] = ai;
        out[1 * HS + i] = bi;
        out[2 * HS + i] = ei;
        out[3 * HS + i] = fi;
        out[4 * HS + i] = dinv;
        e2 = e1; e1 = ei; f2 = f1; f1 = fi; di2 = di1; di1 = dinv;
    }
}

// column solves: one warp-CTA per (b,e, quarter); lane = column j.
// Last CTA per (b,e) also writes the final log10 outputs.
__global__ void __launch_bounds__(32) k_solve(
    const float* __restrict__ GL, const float* __restrict__ GR,
    float* __restrict__ Tout, float* __restrict__ Dout, int BE) {
    __shared__ float2 ys[HS * 32];       // 32KB: per-lane y history
    __shared__ float2 sa[HS], sb[HS], se[HS], sf[HS], sdi[HS];
    __shared__ float  sgl[HS], sgr[HS];
    int blk = blockIdx.x;
    int be = blk >> 2, q = blk & 3;
    int b = be / NEG;
    int lane = threadIdx.x;
    const float2* lu = g_lu + (size_t)be * 5 * HS;
#pragma unroll
    for (int k = 0; k < 4; k++) {
        int i = lane + k * 32;
        sa[i]  = lu[0 * HS + i];
        sb[i]  = lu[1 * HS + i];
        se[i]  = lu[2 * HS + i];
        sf[i]  = lu[3 * HS + i];
        sdi[i] = lu[4 * HS + i];
        sgl[i] = GL[b * HS + i];
        sgr[i] = GR[b * HS + i];
    }
    __syncwarp();

    int j = q * 32 + lane;
    int i0 = q * 32;
    // forward: L y = e_j (y_i = 0 for i < i0 <= j)
    float2 y1 = {0.f, 0.f}, y2 = {0.f, 0.f};
    for (int i = i0; i < HS; i++) {
        float2 y = make_float2((i == j) ? 1.f : 0.f, 0.f);
        CFMS(y, sa[i], y1);
        CFMS(y, sb[i], y2);
        ys[i * 32 + lane] = y;
        y2 = y1; y1 = y;
    }
    // backward: U x = y ; accumulate sum_i gl_i |x_i|^2 and Im x_jj
    float2 x1 = {0.f, 0.f}, x2 = {0.f, 0.f};
    float tp = 0.f, dj = 0.f;
    for (int i = HS - 1; i >= 0; i--) {
        float2 t = (i >= i0) ? ys[i * 32 + lane] : make_float2(0.f, 0.f);
        CFMS(t, se[i], x1);
        CFMS(t, sf[i], x2);
        float2 x; CMUL(x, t, sdi[i]);
        tp = fmaf(sgl[i], fmaf(x.x, x.x, x.y * x.y), tp);
        if (i == j) dj = x.y;
        x2 = x1; x1 = x;
    }
    tp *= sgr[j];
#pragma unroll
    for (int o = 16; o > 0; o >>= 1) {
        tp += __shfl_down_sync(0xffffffffu, tp, o);
        dj += __shfl_down_sync(0xffffffffu, dj, o);
    }
    if (lane == 0) {
        atomicAdd(&g_Tacc[be], tp);
        atomicAdd(&g_Dacc[be], dj);
        __threadfence();
        int old = atomicAdd(&g_cnt[be], 1);
        if (old == 3) {
            __threadfence();
            Tout[be] = log10f(fmaxf(g_Tacc[be], 1e-16f));
            Dout[be] = log10f(fmaxf(-g_Dacc[be] / 3.14159265358979323846f, 1e-16f));
        }
    }
}

// ---------------- launch ----------------------------------------------------
extern "C" void kernel_launch(void* const* d_in, const int* in_sizes, int n_in,
                              void* d_out, int out_size) {
    const float* x      = (const float*)d_in[0];
    const int*   ei     = (const int*)  d_in[1];
    const float* ea     = (const float*)d_in[2];
    const int*   batch  = (const int*)  d_in[3];
    const float* GL     = (const float*)d_in[4];
    const float* GR     = (const float*)d_in[5];
    const float* node_w = (const float*)d_in[6];
    const float* node_b = (const float*)d_in[7];
    const float* edgep_w= (const float*)d_in[8];
    const float* edgep_b= (const float*)d_in[9];
    const float* gat_lin= (const float*)d_in[10];
    const float* att_src= (const float*)d_in[11];
    const float* att_dst= (const float*)d_in[12];
    const float* gat_le = (const float*)d_in[13];
    const float* att_ed = (const float*)d_in[14];
    const float* gat_b  = (const float*)d_in[15];
    const float* ln_s   = (const float*)d_in[16];
    const float* ln_b   = (const float*)d_in[17];
    const float* on_w1  = (const float*)d_in[18];
    const float* on_b1  = (const float*)d_in[19];
    const float* on_w2  = (const float*)d_in[20];
    const float* on_b2  = (const float*)d_in[21];
    const float* cp_w1  = (const float*)d_in[22];
    const float* cp_b1  = (const float*)d_in[23];
    const float* cp_w2  = (const float*)d_in[24];
    const float* cp_b2  = (const float*)d_in[25];

    int N = in_sizes[0] / 4;
    int E = in_sizes[2] / 5;
    int B = in_sizes[4] / HS;
    int BE = B * NEG;
    const int* src = ei;
    const int* dst = ei + E;

    float* out  = (float*)d_out;
    float* Tout = out;
    float* Dout = out + BE;
    float* Hout = out + 2 * BE;

    k_init_h<<<N, HD>>>(x, node_w, node_b);
    k_init_e<<<E, HD>>>(ea, edgep_w, edgep_b);

    int nb_n = (N + 3) / 4, nb_e = (E + 3) / 4;
    for (int l = 0; l < NLAYER; l++) {
        k_attn   <<<nb_n + nb_e, HD>>>(gat_lin + l * HD * HD, att_src + l * HEADS * CDIM,
                                       att_dst + l * HEADS * CDIM, gat_le + l * HD * HD,
                                       att_ed + l * HEADS * CDIM, N, E, nb_n);
        k_edgeagg<<<E + N, HD>>>(src, dst, N, E);
        k_ln     <<<N, HD>>>(gat_b + l * HD, ln_s + l * HD, ln_b + l * HD);
    }

    k_mlp <<<N + E, 64>>>(on_w1, on_b1, on_w2, on_b2, cp_w1, cp_b1, cp_w2, cp_b2, N);
    k_dna <<<1, 1024>>>(x, N, B);
    int tot = N + E + B * HS;
    k_basm<<<(tot + 255) / 256, 256>>>(src, dst, batch, GL, GR, N, E, B);
    k_hwrite<<<(B * HS * HS + 255) / 256, 256>>>(Hout, B);
    k_lu   <<<(BE + 127) / 128, 128>>>(BE);
    k_solve<<<BE * 4, 32>>>(GL, GR, Tout, Dout, BE);
}